// round 12
// baseline (speedup 1.0000x reference)
#include <cuda_runtime.h>
#include <cuda_fp16.h>
#include <cstdint>

#define NN 50000
#define EMAX 800000

// Scratch (no allocations allowed -> __device__ globals)
__device__ __align__(16) int    g_degi[NN];
__device__ __align__(16) int    g_ptr[NN + 1];
__device__ __align__(16) int    g_cursor[NN];
__device__ __align__(16) int    g_esrc[EMAX];
__device__ __align__(16) float  g_dinv[NN];
__device__ __align__(16) __half g_xwh[(size_t)NN * 128];  // x @ W1, fp16 storage
__device__ __align__(16) float  g_tmp[(size_t)NN * 128];  // h = tanh(aggregated + b1)
__device__ __align__(16) __half g_hwh[(size_t)NN * 64];   // h @ W2, fp16 storage

// ---------------------------------------------------------------------------
// CSR build + normalization
// ---------------------------------------------------------------------------
__global__ void zero_kernel(int n) {
    int i = blockIdx.x * blockDim.x + threadIdx.x;
    if (i < n) g_degi[i] = 0;
}

__global__ void hist_kernel(const int* __restrict__ dst, int E) {
    int i = blockIdx.x * blockDim.x + threadIdx.x;
    if (i < E) atomicAdd(&g_degi[dst[i]], 1);
}

// single-block exclusive scan of g_degi -> g_ptr; also cursor=ptr and dinv.
__global__ void scan_kernel() {
    __shared__ int partial[1024];
    const int CH = (NN + 1023) / 1024;
    int t = threadIdx.x;
    int base = t * CH;
    int sum = 0;
    for (int i = 0; i < CH; i++) {
        int idx = base + i;
        if (idx < NN) sum += g_degi[idx];
    }
    partial[t] = sum;
    __syncthreads();
    for (int off = 1; off < 1024; off <<= 1) {
        int v = (t >= off) ? partial[t - off] : 0;
        __syncthreads();
        partial[t] += v;
        __syncthreads();
    }
    int run = (t == 0) ? 0 : partial[t - 1];
    for (int i = 0; i < CH; i++) {
        int idx = base + i;
        if (idx < NN) {
            int d = g_degi[idx];
            g_ptr[idx] = run;
            g_cursor[idx] = run;
            g_dinv[idx] = rsqrtf((float)(d + 1));  // +1 = self loop
            run += d;
        }
    }
    if (t == 1023) g_ptr[NN] = run;
}

__global__ void fill_kernel(const int* __restrict__ src,
                            const int* __restrict__ dst, int E) {
    int i = blockIdx.x * blockDim.x + threadIdx.x;
    if (i >= E) return;
    int d = dst[i];
    int pos = atomicAdd(&g_cursor[d], 1);
    if (pos < EMAX) g_esrc[pos] = src[i];
}

// ---------------------------------------------------------------------------
// TF32 tensor-core GEMM, 2-stage cp.async pipeline.
// C[M,N] = A[M,K] @ B[K,N], row-major; C stored as fp16.
// ---------------------------------------------------------------------------
__device__ __forceinline__ unsigned int f2tf32(float f) {
    unsigned int r;
    asm("cvt.rna.tf32.f32 %0, %1;" : "=r"(r) : "f"(f));
    return r;
}

__device__ __forceinline__ void cp_async16(void* smem, const void* gmem, int pred_sz) {
    unsigned int sa = (unsigned int)__cvta_generic_to_shared(smem);
    asm volatile("cp.async.cg.shared.global [%0], [%1], 16, %2;\n"
                 :: "r"(sa), "l"(gmem), "r"(pred_sz));
}

template <int BM, int BN, int BK, int WM, int WN>
__global__ void __launch_bounds__((BM / WM) * (BN / WN) * 32)
mma_gemm_kernel(const float* __restrict__ A, const float* __restrict__ B,
                __half* __restrict__ C, int M, int N, int K) {
    constexpr int WARPS_M = BM / WM;
    constexpr int WARPS_N = BN / WN;
    constexpr int THREADS = WARPS_M * WARPS_N * 32;
    constexpr int MI = WM / 16;
    constexpr int NI = WN / 8;
    constexpr int APAD = 4, BPAD = 8;

    __shared__ float As[2][BM][BK + APAD];
    __shared__ float Bs[2][BK][BN + BPAD];

    const int tid = threadIdx.x;
    const int warp = tid >> 5;
    const int lane = tid & 31;
    const int g = lane >> 2;
    const int t = lane & 3;
    const int warp_m = warp % WARPS_M;
    const int warp_n = warp / WARPS_M;
    const int block_row = blockIdx.y * BM;

    float acc[MI][NI][4];
#pragma unroll
    for (int mi = 0; mi < MI; mi++)
#pragma unroll
        for (int ni = 0; ni < NI; ni++)
#pragma unroll
            for (int j = 0; j < 4; j++) acc[mi][ni][j] = 0.0f;

    const int KT = K / BK;

    // tile loader via cp.async (counts are in float4 units!)
    auto load_tiles = [&](int kt, int buf) {
        int k0 = kt * BK;
        constexpr int AV = BM * BK / 4;
#pragma unroll
        for (int i = tid; i < AV; i += THREADS) {
            int m = i / (BK / 4);
            int kv = i % (BK / 4);
            int row = block_row + m;
            int rc = row < M ? row : (M - 1);
            cp_async16(&As[buf][m][kv * 4], &A[(size_t)rc * K + k0 + kv * 4],
                       row < M ? 16 : 0);
        }
        constexpr int BV = BK * BN / 4;
#pragma unroll
        for (int i = tid; i < BV; i += THREADS) {
            int k = i / (BN / 4);
            int nv = i % (BN / 4);
            cp_async16(&Bs[buf][k][nv * 4], &B[(size_t)(k0 + k) * N + nv * 4], 16);
        }
    };

    load_tiles(0, 0);
    asm volatile("cp.async.commit_group;\n");

    for (int kt = 0; kt < KT; kt++) {
        asm volatile("cp.async.wait_group 0;\n");
        __syncthreads();
        if (kt + 1 < KT) {
            load_tiles(kt + 1, (kt + 1) & 1);
            asm volatile("cp.async.commit_group;\n");
        }
        int buf = kt & 1;
#pragma unroll
        for (int kk = 0; kk < BK / 8; kk++) {
            unsigned int af[MI][4];
#pragma unroll
            for (int mi = 0; mi < MI; mi++) {
                int r = warp_m * WM + mi * 16;
                af[mi][0] = f2tf32(As[buf][r + g][kk * 8 + t]);
                af[mi][1] = f2tf32(As[buf][r + g + 8][kk * 8 + t]);
                af[mi][2] = f2tf32(As[buf][r + g][kk * 8 + t + 4]);
                af[mi][3] = f2tf32(As[buf][r + g + 8][kk * 8 + t + 4]);
            }
            unsigned int bf[NI][2];
#pragma unroll
            for (int ni = 0; ni < NI; ni++) {
                int c = warp_n * WN + ni * 8 + g;
                bf[ni][0] = f2tf32(Bs[buf][kk * 8 + t][c]);
                bf[ni][1] = f2tf32(Bs[buf][kk * 8 + t + 4][c]);
            }
#pragma unroll
            for (int mi = 0; mi < MI; mi++)
#pragma unroll
                for (int ni = 0; ni < NI; ni++) {
                    asm volatile(
                        "mma.sync.aligned.m16n8k8.row.col.f32.tf32.tf32.f32 "
                        "{%0,%1,%2,%3}, {%4,%5,%6,%7}, {%8,%9}, {%0,%1,%2,%3};"
                        : "+f"(acc[mi][ni][0]), "+f"(acc[mi][ni][1]),
                          "+f"(acc[mi][ni][2]), "+f"(acc[mi][ni][3])
                        : "r"(af[mi][0]), "r"(af[mi][1]), "r"(af[mi][2]), "r"(af[mi][3]),
                          "r"(bf[ni][0]), "r"(bf[ni][1]));
                }
        }
        __syncthreads();
    }

    // ---- epilogue: convert to fp16, store ----
#pragma unroll
    for (int mi = 0; mi < MI; mi++) {
        int r0 = block_row + warp_m * WM + mi * 16 + g;
        int r1 = r0 + 8;
#pragma unroll
        for (int ni = 0; ni < NI; ni++) {
            int c = warp_n * WN + ni * 8 + t * 2;
            if (r0 < M) {
                __half2 hv = __floats2half2_rn(acc[mi][ni][0], acc[mi][ni][1]);
                *(__half2*)&C[(size_t)r0 * N + c] = hv;
            }
            if (r1 < M) {
                __half2 hv = __floats2half2_rn(acc[mi][ni][2], acc[mi][ni][3]);
                *(__half2*)&C[(size_t)r1 * N + c] = hv;
            }
        }
    }
}

// ---------------------------------------------------------------------------
// CSR gather aggregation (no atomics): one warp per node, unroll 4.
// ---------------------------------------------------------------------------
__device__ __forceinline__ void acc_row128(float4& acc, const __half* row,
                                           int lane, float w) {
    uint2 raw = *(const uint2*)&row[lane * 4];
    float2 f0 = __half22float2(*(__half2*)&raw.x);
    float2 f1 = __half22float2(*(__half2*)&raw.y);
    acc.x += f0.x * w; acc.y += f0.y * w; acc.z += f1.x * w; acc.w += f1.y * w;
}

// layer 1: tmp[d,:] = tanh( dinv[d]*sum_s xw[s,:]*dinv[s] + xw[d,:]*dinv[d]^2 + b1 )
__global__ void gather1_kernel(const float* __restrict__ b1) {
    int node = blockIdx.x * (blockDim.x >> 5) + (threadIdx.x >> 5);
    int lane = threadIdx.x & 31;
    if (node >= NN) return;
    int e = g_ptr[node], end = g_ptr[node + 1];
    float dd = g_dinv[node];
    float4 acc = make_float4(0.f, 0.f, 0.f, 0.f);
    for (; e + 4 <= end; e += 4) {
        int s0 = g_esrc[e], s1 = g_esrc[e + 1], s2 = g_esrc[e + 2], s3 = g_esrc[e + 3];
        float w0 = g_dinv[s0], w1 = g_dinv[s1], w2 = g_dinv[s2], w3 = g_dinv[s3];
        acc_row128(acc, &g_xwh[(size_t)s0 * 128], lane, w0);
        acc_row128(acc, &g_xwh[(size_t)s1 * 128], lane, w1);
        acc_row128(acc, &g_xwh[(size_t)s2 * 128], lane, w2);
        acc_row128(acc, &g_xwh[(size_t)s3 * 128], lane, w3);
    }
    for (; e < end; e++) {
        int s = g_esrc[e];
        acc_row128(acc, &g_xwh[(size_t)s * 128], lane, g_dinv[s]);
    }
    float4 self = make_float4(0.f, 0.f, 0.f, 0.f);
    acc_row128(self, &g_xwh[(size_t)node * 128], lane, 1.0f);
    float4 bb = ((const float4*)b1)[lane];
    float dd2 = dd * dd;
    float4 o;
    o.x = tanhf(acc.x * dd + self.x * dd2 + bb.x);
    o.y = tanhf(acc.y * dd + self.y * dd2 + bb.y);
    o.z = tanhf(acc.z * dd + self.z * dd2 + bb.z);
    o.w = tanhf(acc.w * dd + self.w * dd2 + bb.w);
    *(float4*)&g_tmp[(size_t)node * 128 + lane * 4] = o;
}

// layer 2: out[d,:] = dinv[d]*sum_s hw[s,:]*dinv[s] + hw[d,:]*dinv[d]^2 + b2
__global__ void gather2_kernel(const float* __restrict__ b2, float* __restrict__ out) {
    int node = blockIdx.x * (blockDim.x >> 5) + (threadIdx.x >> 5);
    int lane = threadIdx.x & 31;
    if (node >= NN) return;
    int e = g_ptr[node], end = g_ptr[node + 1];
    float dd = g_dinv[node];
    float2 acc = make_float2(0.f, 0.f);
    for (; e + 4 <= end; e += 4) {
        int s0 = g_esrc[e], s1 = g_esrc[e + 1], s2 = g_esrc[e + 2], s3 = g_esrc[e + 3];
        float w0 = g_dinv[s0], w1 = g_dinv[s1], w2 = g_dinv[s2], w3 = g_dinv[s3];
        float2 f0 = __half22float2(*(const __half2*)&g_hwh[(size_t)s0 * 64 + lane * 2]);
        float2 f1 = __half22float2(*(const __half2*)&g_hwh[(size_t)s1 * 64 + lane * 2]);
        float2 f2 = __half22float2(*(const __half2*)&g_hwh[(size_t)s2 * 64 + lane * 2]);
        float2 f3 = __half22float2(*(const __half2*)&g_hwh[(size_t)s3 * 64 + lane * 2]);
        acc.x += f0.x * w0 + f1.x * w1 + f2.x * w2 + f3.x * w3;
        acc.y += f0.y * w0 + f1.y * w1 + f2.y * w2 + f3.y * w3;
    }
    for (; e < end; e++) {
        int s = g_esrc[e];
        float w = g_dinv[s];
        float2 f = __half22float2(*(const __half2*)&g_hwh[(size_t)s * 64 + lane * 2]);
        acc.x += f.x * w; acc.y += f.y * w;
    }
    float2 self = __half22float2(*(const __half2*)&g_hwh[(size_t)node * 64 + lane * 2]);
    float2 bb = ((const float2*)b2)[lane];
    float dd2 = dd * dd;
    float2 o;
    o.x = acc.x * dd + self.x * dd2 + bb.x;
    o.y = acc.y * dd + self.y * dd2 + bb.y;
    *(float2*)&out[(size_t)node * 64 + lane * 2] = o;
}

// ---------------------------------------------------------------------------
extern "C" void kernel_launch(void* const* d_in, const int* in_sizes, int n_in,
                              void* d_out, int out_size) {
    const float* x   = (const float*)d_in[0];
    const int* ei    = (const int*)d_in[1];   // int32 (jax x64 disabled)
    const float* W1  = (const float*)d_in[2];
    const float* b1  = (const float*)d_in[3];
    const float* W2  = (const float*)d_in[4];
    const float* b2  = (const float*)d_in[5];
    float* out       = (float*)d_out;

    const int E = in_sizes[1] / 2;
    const int* src = ei;
    const int* dst = ei + E;

    __half *xwh_p, *hwh_p;
    float *tmp_p;
    cudaGetSymbolAddress((void**)&xwh_p, g_xwh);
    cudaGetSymbolAddress((void**)&tmp_p, g_tmp);
    cudaGetSymbolAddress((void**)&hwh_p, g_hwh);

    const int T = 256;

    // CSR + normalization (dinv/cursor fused into scan)
    zero_kernel<<<(NN + T - 1) / T, T>>>(NN);                 // launch 1
    hist_kernel<<<(E + T - 1) / T, T>>>(dst, E);              // launch 2
    scan_kernel<<<1, 1024>>>();                               // launch 3

    // layer 1 GEMM at launch slot 4 (profiled slot); independent of CSR
    {
        dim3 grid(1, (NN + 63) / 64);
        mma_gemm_kernel<64, 128, 32, 32, 32><<<grid, 256>>>(x, W1, xwh_p, NN, 128, 256);
    }

    fill_kernel<<<(E + T - 1) / T, T>>>(src, dst, E);         // launch 5
    gather1_kernel<<<(NN + 7) / 8, 256>>>(b1);                // launch 6

    // layer 2: hw = h @ W2 (fp16 store)
    {
        dim3 grid(1, (NN + 63) / 64);
        mma_gemm_kernel<64, 64, 32, 32, 16><<<grid, 256>>>(tmp_p, W2, hwh_p, NN, 64, 128);
    }
    gather2_kernel<<<(NN + 7) / 8, 256>>>(b2, out);           // launch 8
}

// round 13
// speedup vs baseline: 1.3347x; 1.3347x over previous
#include <cuda_runtime.h>
#include <cuda_fp16.h>
#include <cstdint>

#define NN 50000
#define EMAX 800000

// Scratch (no allocations allowed -> __device__ globals)
__device__ __align__(16) int    g_degi[NN];
__device__ __align__(16) int    g_ptr[NN + 1];
__device__ __align__(16) int    g_cursor[NN];
__device__ __align__(16) int    g_esrc[EMAX];
__device__ __align__(16) float  g_dinv[NN];
__device__ __align__(16) __half g_xwh[(size_t)NN * 128];  // x @ W1, fp16 storage
__device__ __align__(16) float  g_tmp[(size_t)NN * 128];  // h = tanh(aggregated + b1)
__device__ __align__(16) __half g_hwh[(size_t)NN * 64];   // h @ W2, fp16 storage

// ---------------------------------------------------------------------------
// CSR build + normalization (NOTE: do NOT fuse dinv/cursor into scan_kernel —
// empirically costs +50us, reproduced in R8/R9/R12)
// ---------------------------------------------------------------------------
__global__ void zero_kernel(int n) {
    int i = blockIdx.x * blockDim.x + threadIdx.x;
    if (i < n) { g_degi[i] = 0; g_cursor[i] = 0; }
}

__global__ void hist_kernel(const int* __restrict__ dst, int E) {
    int i = blockIdx.x * blockDim.x + threadIdx.x;
    if (i < E) atomicAdd(&g_degi[dst[i]], 1);
}

// single-block exclusive scan of g_degi -> g_ptr  (g_ptr[NN] = E)
__global__ void scan_kernel() {
    __shared__ int partial[1024];
    const int CH = (NN + 1023) / 1024;
    int t = threadIdx.x;
    int base = t * CH;
    int sum = 0;
    for (int i = 0; i < CH; i++) {
        int idx = base + i;
        if (idx < NN) sum += g_degi[idx];
    }
    partial[t] = sum;
    __syncthreads();
    for (int off = 1; off < 1024; off <<= 1) {
        int v = (t >= off) ? partial[t - off] : 0;
        __syncthreads();
        partial[t] += v;
        __syncthreads();
    }
    int run = (t == 0) ? 0 : partial[t - 1];
    for (int i = 0; i < CH; i++) {
        int idx = base + i;
        if (idx < NN) { g_ptr[idx] = run; run += g_degi[idx]; }
    }
    if (t == 1023) g_ptr[NN] = run;
}

__global__ void dinv_kernel(int n) {
    int i = blockIdx.x * blockDim.x + threadIdx.x;
    if (i < n) g_dinv[i] = rsqrtf((float)(g_degi[i] + 1));  // +1 = self loop
}

__global__ void fill_kernel(const int* __restrict__ src,
                            const int* __restrict__ dst, int E) {
    int i = blockIdx.x * blockDim.x + threadIdx.x;
    if (i >= E) return;
    int d = dst[i];
    int pos = g_ptr[d] + atomicAdd(&g_cursor[d], 1);
    if (pos < EMAX) g_esrc[pos] = src[i];
}

// ---------------------------------------------------------------------------
// TF32 tensor-core GEMM, 2-stage cp.async pipeline.
// C[M,N] = A[M,K] @ B[K,N], row-major; C stored as fp16.
// ---------------------------------------------------------------------------
__device__ __forceinline__ unsigned int f2tf32(float f) {
    unsigned int r;
    asm("cvt.rna.tf32.f32 %0, %1;" : "=r"(r) : "f"(f));
    return r;
}

__device__ __forceinline__ void cp_async16(void* smem, const void* gmem, int pred_sz) {
    unsigned int sa = (unsigned int)__cvta_generic_to_shared(smem);
    asm volatile("cp.async.cg.shared.global [%0], [%1], 16, %2;\n"
                 :: "r"(sa), "l"(gmem), "r"(pred_sz));
}

template <int BM, int BN, int BK, int WM, int WN>
__global__ void __launch_bounds__((BM / WM) * (BN / WN) * 32)
mma_gemm_kernel(const float* __restrict__ A, const float* __restrict__ B,
                __half* __restrict__ C, int M, int N, int K) {
    constexpr int WARPS_M = BM / WM;
    constexpr int WARPS_N = BN / WN;
    constexpr int THREADS = WARPS_M * WARPS_N * 32;
    constexpr int MI = WM / 16;
    constexpr int NI = WN / 8;
    constexpr int APAD = 4, BPAD = 8;

    __shared__ float As[2][BM][BK + APAD];
    __shared__ float Bs[2][BK][BN + BPAD];

    const int tid = threadIdx.x;
    const int warp = tid >> 5;
    const int lane = tid & 31;
    const int g = lane >> 2;
    const int t = lane & 3;
    const int warp_m = warp % WARPS_M;
    const int warp_n = warp / WARPS_M;
    const int block_row = blockIdx.y * BM;

    float acc[MI][NI][4];
#pragma unroll
    for (int mi = 0; mi < MI; mi++)
#pragma unroll
        for (int ni = 0; ni < NI; ni++)
#pragma unroll
            for (int j = 0; j < 4; j++) acc[mi][ni][j] = 0.0f;

    const int KT = K / BK;

    // tile loader via cp.async (counts are in float4 units!)
    auto load_tiles = [&](int kt, int buf) {
        int k0 = kt * BK;
        constexpr int AV = BM * BK / 4;
#pragma unroll
        for (int i = tid; i < AV; i += THREADS) {
            int m = i / (BK / 4);
            int kv = i % (BK / 4);
            int row = block_row + m;
            int rc = row < M ? row : (M - 1);
            cp_async16(&As[buf][m][kv * 4], &A[(size_t)rc * K + k0 + kv * 4],
                       row < M ? 16 : 0);
        }
        constexpr int BV = BK * BN / 4;
#pragma unroll
        for (int i = tid; i < BV; i += THREADS) {
            int k = i / (BN / 4);
            int nv = i % (BN / 4);
            cp_async16(&Bs[buf][k][nv * 4], &B[(size_t)(k0 + k) * N + nv * 4], 16);
        }
    };

    load_tiles(0, 0);
    asm volatile("cp.async.commit_group;\n");

    for (int kt = 0; kt < KT; kt++) {
        asm volatile("cp.async.wait_group 0;\n");
        __syncthreads();
        if (kt + 1 < KT) {
            load_tiles(kt + 1, (kt + 1) & 1);
            asm volatile("cp.async.commit_group;\n");
        }
        int buf = kt & 1;
#pragma unroll
        for (int kk = 0; kk < BK / 8; kk++) {
            unsigned int af[MI][4];
#pragma unroll
            for (int mi = 0; mi < MI; mi++) {
                int r = warp_m * WM + mi * 16;
                af[mi][0] = f2tf32(As[buf][r + g][kk * 8 + t]);
                af[mi][1] = f2tf32(As[buf][r + g + 8][kk * 8 + t]);
                af[mi][2] = f2tf32(As[buf][r + g][kk * 8 + t + 4]);
                af[mi][3] = f2tf32(As[buf][r + g + 8][kk * 8 + t + 4]);
            }
            unsigned int bf[NI][2];
#pragma unroll
            for (int ni = 0; ni < NI; ni++) {
                int c = warp_n * WN + ni * 8 + g;
                bf[ni][0] = f2tf32(Bs[buf][kk * 8 + t][c]);
                bf[ni][1] = f2tf32(Bs[buf][kk * 8 + t + 4][c]);
            }
#pragma unroll
            for (int mi = 0; mi < MI; mi++)
#pragma unroll
                for (int ni = 0; ni < NI; ni++) {
                    asm volatile(
                        "mma.sync.aligned.m16n8k8.row.col.f32.tf32.tf32.f32 "
                        "{%0,%1,%2,%3}, {%4,%5,%6,%7}, {%8,%9}, {%0,%1,%2,%3};"
                        : "+f"(acc[mi][ni][0]), "+f"(acc[mi][ni][1]),
                          "+f"(acc[mi][ni][2]), "+f"(acc[mi][ni][3])
                        : "r"(af[mi][0]), "r"(af[mi][1]), "r"(af[mi][2]), "r"(af[mi][3]),
                          "r"(bf[ni][0]), "r"(bf[ni][1]));
                }
        }
        __syncthreads();
    }

    // ---- epilogue: convert to fp16, store ----
#pragma unroll
    for (int mi = 0; mi < MI; mi++) {
        int r0 = block_row + warp_m * WM + mi * 16 + g;
        int r1 = r0 + 8;
#pragma unroll
        for (int ni = 0; ni < NI; ni++) {
            int c = warp_n * WN + ni * 8 + t * 2;
            if (r0 < M) {
                __half2 hv = __floats2half2_rn(acc[mi][ni][0], acc[mi][ni][1]);
                *(__half2*)&C[(size_t)r0 * N + c] = hv;
            }
            if (r1 < M) {
                __half2 hv = __floats2half2_rn(acc[mi][ni][2], acc[mi][ni][3]);
                *(__half2*)&C[(size_t)r1 * N + c] = hv;
            }
        }
    }
}

// ---------------------------------------------------------------------------
// CSR gather aggregation (no atomics): one warp per node, unroll 4.
// ---------------------------------------------------------------------------
__device__ __forceinline__ void acc_row128(float4& acc, const __half* row,
                                           int lane, float w) {
    uint2 raw = *(const uint2*)&row[lane * 4];
    float2 f0 = __half22float2(*(__half2*)&raw.x);
    float2 f1 = __half22float2(*(__half2*)&raw.y);
    acc.x += f0.x * w; acc.y += f0.y * w; acc.z += f1.x * w; acc.w += f1.y * w;
}

// layer 1: tmp[d,:] = tanh( dinv[d]*sum_s xw[s,:]*dinv[s] + xw[d,:]*dinv[d]^2 + b1 )
__global__ void gather1_kernel(const float* __restrict__ b1) {
    int node = blockIdx.x * (blockDim.x >> 5) + (threadIdx.x >> 5);
    int lane = threadIdx.x & 31;
    if (node >= NN) return;
    int e = g_ptr[node], end = g_ptr[node + 1];
    float dd = g_dinv[node];
    float4 acc = make_float4(0.f, 0.f, 0.f, 0.f);
    for (; e + 4 <= end; e += 4) {
        int s0 = g_esrc[e], s1 = g_esrc[e + 1], s2 = g_esrc[e + 2], s3 = g_esrc[e + 3];
        float w0 = g_dinv[s0], w1 = g_dinv[s1], w2 = g_dinv[s2], w3 = g_dinv[s3];
        acc_row128(acc, &g_xwh[(size_t)s0 * 128], lane, w0);
        acc_row128(acc, &g_xwh[(size_t)s1 * 128], lane, w1);
        acc_row128(acc, &g_xwh[(size_t)s2 * 128], lane, w2);
        acc_row128(acc, &g_xwh[(size_t)s3 * 128], lane, w3);
    }
    for (; e < end; e++) {
        int s = g_esrc[e];
        acc_row128(acc, &g_xwh[(size_t)s * 128], lane, g_dinv[s]);
    }
    float4 self = make_float4(0.f, 0.f, 0.f, 0.f);
    acc_row128(self, &g_xwh[(size_t)node * 128], lane, 1.0f);
    float4 bb = ((const float4*)b1)[lane];
    float dd2 = dd * dd;
    float4 o;
    o.x = tanhf(acc.x * dd + self.x * dd2 + bb.x);
    o.y = tanhf(acc.y * dd + self.y * dd2 + bb.y);
    o.z = tanhf(acc.z * dd + self.z * dd2 + bb.z);
    o.w = tanhf(acc.w * dd + self.w * dd2 + bb.w);
    *(float4*)&g_tmp[(size_t)node * 128 + lane * 4] = o;
}

// layer 2: out[d,:] = dinv[d]*sum_s hw[s,:]*dinv[s] + hw[d,:]*dinv[d]^2 + b2
__global__ void gather2_kernel(const float* __restrict__ b2, float* __restrict__ out) {
    int node = blockIdx.x * (blockDim.x >> 5) + (threadIdx.x >> 5);
    int lane = threadIdx.x & 31;
    if (node >= NN) return;
    int e = g_ptr[node], end = g_ptr[node + 1];
    float dd = g_dinv[node];
    float2 acc = make_float2(0.f, 0.f);
    for (; e + 4 <= end; e += 4) {
        int s0 = g_esrc[e], s1 = g_esrc[e + 1], s2 = g_esrc[e + 2], s3 = g_esrc[e + 3];
        float w0 = g_dinv[s0], w1 = g_dinv[s1], w2 = g_dinv[s2], w3 = g_dinv[s3];
        float2 f0 = __half22float2(*(const __half2*)&g_hwh[(size_t)s0 * 64 + lane * 2]);
        float2 f1 = __half22float2(*(const __half2*)&g_hwh[(size_t)s1 * 64 + lane * 2]);
        float2 f2 = __half22float2(*(const __half2*)&g_hwh[(size_t)s2 * 64 + lane * 2]);
        float2 f3 = __half22float2(*(const __half2*)&g_hwh[(size_t)s3 * 64 + lane * 2]);
        acc.x += f0.x * w0 + f1.x * w1 + f2.x * w2 + f3.x * w3;
        acc.y += f0.y * w0 + f1.y * w1 + f2.y * w2 + f3.y * w3;
    }
    for (; e < end; e++) {
        int s = g_esrc[e];
        float w = g_dinv[s];
        float2 f = __half22float2(*(const __half2*)&g_hwh[(size_t)s * 64 + lane * 2]);
        acc.x += f.x * w; acc.y += f.y * w;
    }
    float2 self = __half22float2(*(const __half2*)&g_hwh[(size_t)node * 64 + lane * 2]);
    float2 bb = ((const float2*)b2)[lane];
    float dd2 = dd * dd;
    float2 o;
    o.x = acc.x * dd + self.x * dd2 + bb.x;
    o.y = acc.y * dd + self.y * dd2 + bb.y;
    *(float2*)&out[(size_t)node * 64 + lane * 2] = o;
}

// ---------------------------------------------------------------------------
extern "C" void kernel_launch(void* const* d_in, const int* in_sizes, int n_in,
                              void* d_out, int out_size) {
    const float* x   = (const float*)d_in[0];
    const int* ei    = (const int*)d_in[1];   // int32 (jax x64 disabled)
    const float* W1  = (const float*)d_in[2];
    const float* b1  = (const float*)d_in[3];
    const float* W2  = (const float*)d_in[4];
    const float* b2  = (const float*)d_in[5];
    float* out       = (float*)d_out;

    const int E = in_sizes[1] / 2;
    const int* src = ei;
    const int* dst = ei + E;

    __half *xwh_p, *hwh_p;
    float *tmp_p;
    cudaGetSymbolAddress((void**)&xwh_p, g_xwh);
    cudaGetSymbolAddress((void**)&tmp_p, g_tmp);
    cudaGetSymbolAddress((void**)&hwh_p, g_hwh);

    // lazily-created side stream + fork/join events (host objects, no device mem)
    static cudaStream_t s2 = nullptr;
    static cudaEvent_t ev_fork = nullptr, ev_join = nullptr;
    if (!s2) {
        cudaStreamCreateWithFlags(&s2, cudaStreamNonBlocking);
        cudaEventCreateWithFlags(&ev_fork, cudaEventDisableTiming);
        cudaEventCreateWithFlags(&ev_join, cudaEventDisableTiming);
    }

    const int T = 256;

    // ---- fork: GEMM1 (independent of CSR build) runs on s2 ----
    cudaEventRecord(ev_fork, 0);
    cudaStreamWaitEvent(s2, ev_fork, 0);
    {
        dim3 grid(1, (NN + 63) / 64);
        mma_gemm_kernel<64, 128, 32, 32, 32><<<grid, 256, 0, s2>>>(
            x, W1, xwh_p, NN, 128, 256);
    }
    cudaEventRecord(ev_join, s2);

    // ---- CSR build chain on default stream (concurrent with GEMM1) ----
    zero_kernel<<<(NN + T - 1) / T, T>>>(NN);
    hist_kernel<<<(E + T - 1) / T, T>>>(dst, E);
    scan_kernel<<<1, 1024>>>();
    dinv_kernel<<<(NN + T - 1) / T, T>>>(NN);
    fill_kernel<<<(E + T - 1) / T, T>>>(src, dst, E);

    // ---- join: gather1 needs both chains ----
    cudaStreamWaitEvent(0, ev_join, 0);
    gather1_kernel<<<(NN + 7) / 8, 256>>>(b1);

    // layer 2: hw = h @ W2 (fp16 store)
    {
        dim3 grid(1, (NN + 63) / 64);
        mma_gemm_kernel<64, 64, 32, 32, 16><<<grid, 256>>>(tmp_p, W2, hwh_p, NN, 64, 128);
    }
    gather2_kernel<<<(NN + 7) / 8, 256>>>(b2, out);
}

// round 14
// speedup vs baseline: 1.8504x; 1.3864x over previous
#include <cuda_runtime.h>
#include <cuda_fp16.h>
#include <cstdint>

#define NN 50000
#define EMAX 800000
#define NB ((NN + 255) / 256)   // 196 scan blocks

// Scratch (no allocations allowed -> __device__ globals)
__device__ __align__(16) int    g_degi[NN];
__device__ __align__(16) int    g_ptr[NN + 1];
__device__ __align__(16) int    g_cursor[NN];
__device__ __align__(16) int    g_esrc[EMAX];
__device__ __align__(16) int    g_blocksum[NB];
__device__ __align__(16) int    g_blockoff[NB];
__device__ __align__(16) float  g_dinv[NN];
__device__ __align__(16) __half g_xwh[(size_t)NN * 128];  // x @ W1, fp16 storage
__device__ __align__(16) float  g_tmp[(size_t)NN * 128];  // h = tanh(aggregated + b1)
__device__ __align__(16) __half g_hwh[(size_t)NN * 64];   // h @ W2, fp16 storage

// ---------------------------------------------------------------------------
// CSR build + normalization — parallel 3-stage scan (old 1-block scan was 52us)
// ---------------------------------------------------------------------------
__global__ void zero_kernel(int n) {
    int i = blockIdx.x * blockDim.x + threadIdx.x;
    if (i < n) g_degi[i] = 0;
}

__global__ void hist_kernel(const int* __restrict__ dst, int E) {
    int i = blockIdx.x * blockDim.x + threadIdx.x;
    if (i < E) atomicAdd(&g_degi[dst[i]], 1);
}

// stage A: per-block sums of g_degi (256 elements per block)
__global__ void scanA_kernel() {
    __shared__ int s[256];
    int t = threadIdx.x;
    int i = blockIdx.x * 256 + t;
    s[t] = (i < NN) ? g_degi[i] : 0;
    __syncthreads();
    for (int off = 128; off > 0; off >>= 1) {
        if (t < off) s[t] += s[t + off];
        __syncthreads();
    }
    if (t == 0) g_blocksum[blockIdx.x] = s[0];
}

// stage B: single-block exclusive scan of NB block sums (tiny)
__global__ void scanB_kernel() {
    __shared__ int s[256];
    int t = threadIdx.x;
    int v = (t < NB) ? g_blocksum[t] : 0;
    s[t] = v;
    __syncthreads();
    for (int off = 1; off < 256; off <<= 1) {
        int add = (t >= off) ? s[t - off] : 0;
        __syncthreads();
        s[t] += add;
        __syncthreads();
    }
    if (t < NB) g_blockoff[t] = s[t] - v;      // exclusive
    if (t == NB - 1) g_ptr[NN] = s[t];         // total = E
}

// stage C: in-block exclusive scan + block offset -> ptr/cursor; dinv
__global__ void scanC_kernel() {
    __shared__ int s[256];
    int t = threadIdx.x;
    int i = blockIdx.x * 256 + t;
    int v = (i < NN) ? g_degi[i] : 0;
    s[t] = v;
    __syncthreads();
    for (int off = 1; off < 256; off <<= 1) {
        int add = (t >= off) ? s[t - off] : 0;
        __syncthreads();
        s[t] += add;
        __syncthreads();
    }
    if (i < NN) {
        int p = g_blockoff[blockIdx.x] + s[t] - v;  // global exclusive prefix
        g_ptr[i] = p;
        g_cursor[i] = p;
        g_dinv[i] = rsqrtf((float)(v + 1));         // +1 = self loop
    }
}

__global__ void fill_kernel(const int* __restrict__ src,
                            const int* __restrict__ dst, int E) {
    int i = blockIdx.x * blockDim.x + threadIdx.x;
    if (i >= E) return;
    int d = dst[i];
    int pos = atomicAdd(&g_cursor[d], 1);
    if (pos < EMAX) g_esrc[pos] = src[i];
}

// ---------------------------------------------------------------------------
// TF32 tensor-core GEMM, 2-stage cp.async pipeline.
// C[M,N] = A[M,K] @ B[K,N], row-major; C stored as fp16.
// ---------------------------------------------------------------------------
__device__ __forceinline__ unsigned int f2tf32(float f) {
    unsigned int r;
    asm("cvt.rna.tf32.f32 %0, %1;" : "=r"(r) : "f"(f));
    return r;
}

__device__ __forceinline__ void cp_async16(void* smem, const void* gmem, int pred_sz) {
    unsigned int sa = (unsigned int)__cvta_generic_to_shared(smem);
    asm volatile("cp.async.cg.shared.global [%0], [%1], 16, %2;\n"
                 :: "r"(sa), "l"(gmem), "r"(pred_sz));
}

template <int BM, int BN, int BK, int WM, int WN>
__global__ void __launch_bounds__((BM / WM) * (BN / WN) * 32)
mma_gemm_kernel(const float* __restrict__ A, const float* __restrict__ B,
                __half* __restrict__ C, int M, int N, int K) {
    constexpr int WARPS_M = BM / WM;
    constexpr int WARPS_N = BN / WN;
    constexpr int THREADS = WARPS_M * WARPS_N * 32;
    constexpr int MI = WM / 16;
    constexpr int NI = WN / 8;
    constexpr int APAD = 4, BPAD = 8;

    __shared__ float As[2][BM][BK + APAD];
    __shared__ float Bs[2][BK][BN + BPAD];

    const int tid = threadIdx.x;
    const int warp = tid >> 5;
    const int lane = tid & 31;
    const int g = lane >> 2;
    const int t = lane & 3;
    const int warp_m = warp % WARPS_M;
    const int warp_n = warp / WARPS_M;
    const int block_row = blockIdx.y * BM;

    float acc[MI][NI][4];
#pragma unroll
    for (int mi = 0; mi < MI; mi++)
#pragma unroll
        for (int ni = 0; ni < NI; ni++)
#pragma unroll
            for (int j = 0; j < 4; j++) acc[mi][ni][j] = 0.0f;

    const int KT = K / BK;

    // tile loader via cp.async (counts are in float4 units!)
    auto load_tiles = [&](int kt, int buf) {
        int k0 = kt * BK;
        constexpr int AV = BM * BK / 4;
#pragma unroll
        for (int i = tid; i < AV; i += THREADS) {
            int m = i / (BK / 4);
            int kv = i % (BK / 4);
            int row = block_row + m;
            int rc = row < M ? row : (M - 1);
            cp_async16(&As[buf][m][kv * 4], &A[(size_t)rc * K + k0 + kv * 4],
                       row < M ? 16 : 0);
        }
        constexpr int BV = BK * BN / 4;
#pragma unroll
        for (int i = tid; i < BV; i += THREADS) {
            int k = i / (BN / 4);
            int nv = i % (BN / 4);
            cp_async16(&Bs[buf][k][nv * 4], &B[(size_t)(k0 + k) * N + nv * 4], 16);
        }
    };

    load_tiles(0, 0);
    asm volatile("cp.async.commit_group;\n");

    for (int kt = 0; kt < KT; kt++) {
        asm volatile("cp.async.wait_group 0;\n");
        __syncthreads();
        if (kt + 1 < KT) {
            load_tiles(kt + 1, (kt + 1) & 1);
            asm volatile("cp.async.commit_group;\n");
        }
        int buf = kt & 1;
#pragma unroll
        for (int kk = 0; kk < BK / 8; kk++) {
            unsigned int af[MI][4];
#pragma unroll
            for (int mi = 0; mi < MI; mi++) {
                int r = warp_m * WM + mi * 16;
                af[mi][0] = f2tf32(As[buf][r + g][kk * 8 + t]);
                af[mi][1] = f2tf32(As[buf][r + g + 8][kk * 8 + t]);
                af[mi][2] = f2tf32(As[buf][r + g][kk * 8 + t + 4]);
                af[mi][3] = f2tf32(As[buf][r + g + 8][kk * 8 + t + 4]);
            }
            unsigned int bf[NI][2];
#pragma unroll
            for (int ni = 0; ni < NI; ni++) {
                int c = warp_n * WN + ni * 8 + g;
                bf[ni][0] = f2tf32(Bs[buf][kk * 8 + t][c]);
                bf[ni][1] = f2tf32(Bs[buf][kk * 8 + t + 4][c]);
            }
#pragma unroll
            for (int mi = 0; mi < MI; mi++)
#pragma unroll
                for (int ni = 0; ni < NI; ni++) {
                    asm volatile(
                        "mma.sync.aligned.m16n8k8.row.col.f32.tf32.tf32.f32 "
                        "{%0,%1,%2,%3}, {%4,%5,%6,%7}, {%8,%9}, {%0,%1,%2,%3};"
                        : "+f"(acc[mi][ni][0]), "+f"(acc[mi][ni][1]),
                          "+f"(acc[mi][ni][2]), "+f"(acc[mi][ni][3])
                        : "r"(af[mi][0]), "r"(af[mi][1]), "r"(af[mi][2]), "r"(af[mi][3]),
                          "r"(bf[ni][0]), "r"(bf[ni][1]));
                }
        }
        __syncthreads();
    }

    // ---- epilogue: convert to fp16, store ----
#pragma unroll
    for (int mi = 0; mi < MI; mi++) {
        int r0 = block_row + warp_m * WM + mi * 16 + g;
        int r1 = r0 + 8;
#pragma unroll
        for (int ni = 0; ni < NI; ni++) {
            int c = warp_n * WN + ni * 8 + t * 2;
            if (r0 < M) {
                __half2 hv = __floats2half2_rn(acc[mi][ni][0], acc[mi][ni][1]);
                *(__half2*)&C[(size_t)r0 * N + c] = hv;
            }
            if (r1 < M) {
                __half2 hv = __floats2half2_rn(acc[mi][ni][2], acc[mi][ni][3]);
                *(__half2*)&C[(size_t)r1 * N + c] = hv;
            }
        }
    }
}

// ---------------------------------------------------------------------------
// CSR gather aggregation (no atomics): one warp per node, unroll 4.
// ---------------------------------------------------------------------------
__device__ __forceinline__ void acc_row128(float4& acc, const __half* row,
                                           int lane, float w) {
    uint2 raw = *(const uint2*)&row[lane * 4];
    float2 f0 = __half22float2(*(__half2*)&raw.x);
    float2 f1 = __half22float2(*(__half2*)&raw.y);
    acc.x += f0.x * w; acc.y += f0.y * w; acc.z += f1.x * w; acc.w += f1.y * w;
}

// layer 1: tmp[d,:] = tanh( dinv[d]*sum_s xw[s,:]*dinv[s] + xw[d,:]*dinv[d]^2 + b1 )
__global__ void gather1_kernel(const float* __restrict__ b1) {
    int node = blockIdx.x * (blockDim.x >> 5) + (threadIdx.x >> 5);
    int lane = threadIdx.x & 31;
    if (node >= NN) return;
    int e = g_ptr[node], end = g_ptr[node + 1];
    float dd = g_dinv[node];
    float4 acc = make_float4(0.f, 0.f, 0.f, 0.f);
    for (; e + 4 <= end; e += 4) {
        int s0 = g_esrc[e], s1 = g_esrc[e + 1], s2 = g_esrc[e + 2], s3 = g_esrc[e + 3];
        float w0 = g_dinv[s0], w1 = g_dinv[s1], w2 = g_dinv[s2], w3 = g_dinv[s3];
        acc_row128(acc, &g_xwh[(size_t)s0 * 128], lane, w0);
        acc_row128(acc, &g_xwh[(size_t)s1 * 128], lane, w1);
        acc_row128(acc, &g_xwh[(size_t)s2 * 128], lane, w2);
        acc_row128(acc, &g_xwh[(size_t)s3 * 128], lane, w3);
    }
    for (; e < end; e++) {
        int s = g_esrc[e];
        acc_row128(acc, &g_xwh[(size_t)s * 128], lane, g_dinv[s]);
    }
    float4 self = make_float4(0.f, 0.f, 0.f, 0.f);
    acc_row128(self, &g_xwh[(size_t)node * 128], lane, 1.0f);
    float4 bb = ((const float4*)b1)[lane];
    float dd2 = dd * dd;
    float4 o;
    o.x = tanhf(acc.x * dd + self.x * dd2 + bb.x);
    o.y = tanhf(acc.y * dd + self.y * dd2 + bb.y);
    o.z = tanhf(acc.z * dd + self.z * dd2 + bb.z);
    o.w = tanhf(acc.w * dd + self.w * dd2 + bb.w);
    *(float4*)&g_tmp[(size_t)node * 128 + lane * 4] = o;
}

// layer 2: out[d,:] = dinv[d]*sum_s hw[s,:]*dinv[s] + hw[d,:]*dinv[d]^2 + b2
__global__ void gather2_kernel(const float* __restrict__ b2, float* __restrict__ out) {
    int node = blockIdx.x * (blockDim.x >> 5) + (threadIdx.x >> 5);
    int lane = threadIdx.x & 31;
    if (node >= NN) return;
    int e = g_ptr[node], end = g_ptr[node + 1];
    float dd = g_dinv[node];
    float2 acc = make_float2(0.f, 0.f);
    for (; e + 4 <= end; e += 4) {
        int s0 = g_esrc[e], s1 = g_esrc[e + 1], s2 = g_esrc[e + 2], s3 = g_esrc[e + 3];
        float w0 = g_dinv[s0], w1 = g_dinv[s1], w2 = g_dinv[s2], w3 = g_dinv[s3];
        float2 f0 = __half22float2(*(const __half2*)&g_hwh[(size_t)s0 * 64 + lane * 2]);
        float2 f1 = __half22float2(*(const __half2*)&g_hwh[(size_t)s1 * 64 + lane * 2]);
        float2 f2 = __half22float2(*(const __half2*)&g_hwh[(size_t)s2 * 64 + lane * 2]);
        float2 f3 = __half22float2(*(const __half2*)&g_hwh[(size_t)s3 * 64 + lane * 2]);
        acc.x += f0.x * w0 + f1.x * w1 + f2.x * w2 + f3.x * w3;
        acc.y += f0.y * w0 + f1.y * w1 + f2.y * w2 + f3.y * w3;
    }
    for (; e < end; e++) {
        int s = g_esrc[e];
        float w = g_dinv[s];
        float2 f = __half22float2(*(const __half2*)&g_hwh[(size_t)s * 64 + lane * 2]);
        acc.x += f.x * w; acc.y += f.y * w;
    }
    float2 self = __half22float2(*(const __half2*)&g_hwh[(size_t)node * 64 + lane * 2]);
    float2 bb = ((const float2*)b2)[lane];
    float dd2 = dd * dd;
    float2 o;
    o.x = acc.x * dd + self.x * dd2 + bb.x;
    o.y = acc.y * dd + self.y * dd2 + bb.y;
    *(float2*)&out[(size_t)node * 64 + lane * 2] = o;
}

// ---------------------------------------------------------------------------
extern "C" void kernel_launch(void* const* d_in, const int* in_sizes, int n_in,
                              void* d_out, int out_size) {
    const float* x   = (const float*)d_in[0];
    const int* ei    = (const int*)d_in[1];   // int32 (jax x64 disabled)
    const float* W1  = (const float*)d_in[2];
    const float* b1  = (const float*)d_in[3];
    const float* W2  = (const float*)d_in[4];
    const float* b2  = (const float*)d_in[5];
    float* out       = (float*)d_out;

    const int E = in_sizes[1] / 2;
    const int* src = ei;
    const int* dst = ei + E;

    __half *xwh_p, *hwh_p;
    float *tmp_p;
    cudaGetSymbolAddress((void**)&xwh_p, g_xwh);
    cudaGetSymbolAddress((void**)&tmp_p, g_tmp);
    cudaGetSymbolAddress((void**)&hwh_p, g_hwh);

    // lazily-created side stream + fork/join events (host objects, no device mem)
    static cudaStream_t s2 = nullptr;
    static cudaEvent_t ev_fork = nullptr, ev_join = nullptr;
    if (!s2) {
        cudaStreamCreateWithFlags(&s2, cudaStreamNonBlocking);
        cudaEventCreateWithFlags(&ev_fork, cudaEventDisableTiming);
        cudaEventCreateWithFlags(&ev_join, cudaEventDisableTiming);
    }

    const int T = 256;

    // ---- fork: GEMM1 (independent of CSR build) runs on s2 ----
    cudaEventRecord(ev_fork, 0);
    cudaStreamWaitEvent(s2, ev_fork, 0);
    {
        dim3 grid(1, (NN + 63) / 64);
        mma_gemm_kernel<64, 128, 32, 32, 32><<<grid, 256, 0, s2>>>(
            x, W1, xwh_p, NN, 128, 256);
    }
    cudaEventRecord(ev_join, s2);

    // ---- CSR build chain on default stream (concurrent with GEMM1) ----
    zero_kernel<<<(NN + T - 1) / T, T>>>(NN);
    hist_kernel<<<(E + T - 1) / T, T>>>(dst, E);
    scanA_kernel<<<NB, 256>>>();
    scanB_kernel<<<1, 256>>>();
    scanC_kernel<<<NB, 256>>>();
    fill_kernel<<<(E + T - 1) / T, T>>>(src, dst, E);

    // ---- join: gather1 needs both chains ----
    cudaStreamWaitEvent(0, ev_join, 0);
    gather1_kernel<<<(NN + 7) / 8, 256>>>(b1);

    // layer 2: hw = h @ W2 (fp16 store)
    {
        dim3 grid(1, (NN + 63) / 64);
        mma_gemm_kernel<64, 64, 32, 32, 16><<<grid, 256>>>(tmp_p, W2, hwh_p, NN, 64, 128);
    }
    gather2_kernel<<<(NN + 7) / 8, 256>>>(b2, out);
}

// round 15
// speedup vs baseline: 1.8809x; 1.0164x over previous
#include <cuda_runtime.h>
#include <cuda_fp16.h>
#include <cstdint>

#define NN 50000
#define EMAX 800000
#define NB ((NN + 255) / 256)   // 196 scan blocks

// Scratch (no allocations allowed -> __device__ globals)
__device__ __align__(16) int    g_degi[NN];
__device__ __align__(16) int    g_ptr[NN + 1];
__device__ __align__(16) int    g_cursor[NN];
__device__ __align__(16) int    g_esrc[EMAX];
__device__ __align__(16) int    g_blocksum[NB];
__device__ __align__(16) float  g_dinv[NN];
__device__ __align__(16) __half g_xwh[(size_t)NN * 128];  // x @ W1, fp16 storage
__device__ __align__(16) float  g_tmp[(size_t)NN * 128];  // h = tanh(aggregated + b1)
__device__ __align__(16) __half g_hwh[(size_t)NN * 64];   // h @ W2, fp16 storage

// ---------------------------------------------------------------------------
// CSR build + normalization — parallel 2-stage scan
// ---------------------------------------------------------------------------
__global__ void zero_kernel(int n) {
    int i = blockIdx.x * blockDim.x + threadIdx.x;
    if (i < n) g_degi[i] = 0;
}

__global__ void hist_kernel(const int* __restrict__ dst, int E) {
    int i = (blockIdx.x * blockDim.x + threadIdx.x) * 4;
    if (i + 3 < E) {
        int4 d = *(const int4*)&dst[i];
        atomicAdd(&g_degi[d.x], 1);
        atomicAdd(&g_degi[d.y], 1);
        atomicAdd(&g_degi[d.z], 1);
        atomicAdd(&g_degi[d.w], 1);
    } else {
        for (; i < E; i++) atomicAdd(&g_degi[dst[i]], 1);
    }
}

// stage A: per-block sums of g_degi (256 elements per block)
__global__ void scanA_kernel() {
    __shared__ int s[256];
    int t = threadIdx.x;
    int i = blockIdx.x * 256 + t;
    s[t] = (i < NN) ? g_degi[i] : 0;
    __syncthreads();
    for (int off = 128; off > 0; off >>= 1) {
        if (t < off) s[t] += s[t + off];
        __syncthreads();
    }
    if (t == 0) g_blocksum[blockIdx.x] = s[0];
}

// stage C: every block redundantly scans the 196 block sums (cheap), then
// in-block exclusive scan + offset -> ptr/cursor; also dinv.
__global__ void scanC_kernel() {
    __shared__ int bs[256];
    __shared__ int s[256];
    int t = threadIdx.x;

    // inclusive scan of block sums (all blocks do the same tiny scan)
    int bv = (t < NB) ? g_blocksum[t] : 0;
    bs[t] = bv;
    __syncthreads();
    for (int off = 1; off < 256; off <<= 1) {
        int add = (t >= off) ? bs[t - off] : 0;
        __syncthreads();
        bs[t] += add;
        __syncthreads();
    }
    int blockoff = (blockIdx.x == 0) ? 0 : bs[blockIdx.x - 1];

    // local inclusive scan of this block's 256 degrees
    int i = blockIdx.x * 256 + t;
    int v = (i < NN) ? g_degi[i] : 0;
    s[t] = v;
    __syncthreads();
    for (int off = 1; off < 256; off <<= 1) {
        int add = (t >= off) ? s[t - off] : 0;
        __syncthreads();
        s[t] += add;
        __syncthreads();
    }
    if (i < NN) {
        int p = blockoff + s[t] - v;  // global exclusive prefix
        g_ptr[i] = p;
        g_cursor[i] = p;
        g_dinv[i] = rsqrtf((float)(v + 1));  // +1 = self loop
    }
    if (blockIdx.x == 0 && t == 0) g_ptr[NN] = bs[NB - 1];  // total = E
}

__global__ void fill_kernel(const int* __restrict__ src,
                            const int* __restrict__ dst, int E) {
    int i = (blockIdx.x * blockDim.x + threadIdx.x) * 4;
    if (i + 3 < E) {
        int4 s = *(const int4*)&src[i];
        int4 d = *(const int4*)&dst[i];
        int p0 = atomicAdd(&g_cursor[d.x], 1);
        int p1 = atomicAdd(&g_cursor[d.y], 1);
        int p2 = atomicAdd(&g_cursor[d.z], 1);
        int p3 = atomicAdd(&g_cursor[d.w], 1);
        g_esrc[p0] = s.x;
        g_esrc[p1] = s.y;
        g_esrc[p2] = s.z;
        g_esrc[p3] = s.w;
    } else {
        for (; i < E; i++) {
            int p = atomicAdd(&g_cursor[dst[i]], 1);
            g_esrc[p] = src[i];
        }
    }
}

// ---------------------------------------------------------------------------
// TF32 tensor-core GEMM, 2-stage cp.async pipeline.
// C[M,N] = A[M,K] @ B[K,N], row-major; C stored as fp16.
// ---------------------------------------------------------------------------
__device__ __forceinline__ unsigned int f2tf32(float f) {
    unsigned int r;
    asm("cvt.rna.tf32.f32 %0, %1;" : "=r"(r) : "f"(f));
    return r;
}

__device__ __forceinline__ void cp_async16(void* smem, const void* gmem, int pred_sz) {
    unsigned int sa = (unsigned int)__cvta_generic_to_shared(smem);
    asm volatile("cp.async.cg.shared.global [%0], [%1], 16, %2;\n"
                 :: "r"(sa), "l"(gmem), "r"(pred_sz));
}

template <int BM, int BN, int BK, int WM, int WN>
__global__ void __launch_bounds__((BM / WM) * (BN / WN) * 32)
mma_gemm_kernel(const float* __restrict__ A, const float* __restrict__ B,
                __half* __restrict__ C, int M, int N, int K) {
    constexpr int WARPS_M = BM / WM;
    constexpr int WARPS_N = BN / WN;
    constexpr int THREADS = WARPS_M * WARPS_N * 32;
    constexpr int MI = WM / 16;
    constexpr int NI = WN / 8;
    constexpr int APAD = 4, BPAD = 8;

    __shared__ float As[2][BM][BK + APAD];
    __shared__ float Bs[2][BK][BN + BPAD];

    const int tid = threadIdx.x;
    const int warp = tid >> 5;
    const int lane = tid & 31;
    const int g = lane >> 2;
    const int t = lane & 3;
    const int warp_m = warp % WARPS_M;
    const int warp_n = warp / WARPS_M;
    const int block_row = blockIdx.y * BM;

    float acc[MI][NI][4];
#pragma unroll
    for (int mi = 0; mi < MI; mi++)
#pragma unroll
        for (int ni = 0; ni < NI; ni++)
#pragma unroll
            for (int j = 0; j < 4; j++) acc[mi][ni][j] = 0.0f;

    const int KT = K / BK;

    // tile loader via cp.async (counts are in float4 units!)
    auto load_tiles = [&](int kt, int buf) {
        int k0 = kt * BK;
        constexpr int AV = BM * BK / 4;
#pragma unroll
        for (int i = tid; i < AV; i += THREADS) {
            int m = i / (BK / 4);
            int kv = i % (BK / 4);
            int row = block_row + m;
            int rc = row < M ? row : (M - 1);
            cp_async16(&As[buf][m][kv * 4], &A[(size_t)rc * K + k0 + kv * 4],
                       row < M ? 16 : 0);
        }
        constexpr int BV = BK * BN / 4;
#pragma unroll
        for (int i = tid; i < BV; i += THREADS) {
            int k = i / (BN / 4);
            int nv = i % (BN / 4);
            cp_async16(&Bs[buf][k][nv * 4], &B[(size_t)(k0 + k) * N + nv * 4], 16);
        }
    };

    load_tiles(0, 0);
    asm volatile("cp.async.commit_group;\n");

    for (int kt = 0; kt < KT; kt++) {
        asm volatile("cp.async.wait_group 0;\n");
        __syncthreads();
        if (kt + 1 < KT) {
            load_tiles(kt + 1, (kt + 1) & 1);
            asm volatile("cp.async.commit_group;\n");
        }
        int buf = kt & 1;
#pragma unroll
        for (int kk = 0; kk < BK / 8; kk++) {
            unsigned int af[MI][4];
#pragma unroll
            for (int mi = 0; mi < MI; mi++) {
                int r = warp_m * WM + mi * 16;
                af[mi][0] = f2tf32(As[buf][r + g][kk * 8 + t]);
                af[mi][1] = f2tf32(As[buf][r + g + 8][kk * 8 + t]);
                af[mi][2] = f2tf32(As[buf][r + g][kk * 8 + t + 4]);
                af[mi][3] = f2tf32(As[buf][r + g + 8][kk * 8 + t + 4]);
            }
            unsigned int bf[NI][2];
#pragma unroll
            for (int ni = 0; ni < NI; ni++) {
                int c = warp_n * WN + ni * 8 + g;
                bf[ni][0] = f2tf32(Bs[buf][kk * 8 + t][c]);
                bf[ni][1] = f2tf32(Bs[buf][kk * 8 + t + 4][c]);
            }
#pragma unroll
            for (int mi = 0; mi < MI; mi++)
#pragma unroll
                for (int ni = 0; ni < NI; ni++) {
                    asm volatile(
                        "mma.sync.aligned.m16n8k8.row.col.f32.tf32.tf32.f32 "
                        "{%0,%1,%2,%3}, {%4,%5,%6,%7}, {%8,%9}, {%0,%1,%2,%3};"
                        : "+f"(acc[mi][ni][0]), "+f"(acc[mi][ni][1]),
                          "+f"(acc[mi][ni][2]), "+f"(acc[mi][ni][3])
                        : "r"(af[mi][0]), "r"(af[mi][1]), "r"(af[mi][2]), "r"(af[mi][3]),
                          "r"(bf[ni][0]), "r"(bf[ni][1]));
                }
        }
        __syncthreads();
    }

    // ---- epilogue: convert to fp16, store ----
#pragma unroll
    for (int mi = 0; mi < MI; mi++) {
        int r0 = block_row + warp_m * WM + mi * 16 + g;
        int r1 = r0 + 8;
#pragma unroll
        for (int ni = 0; ni < NI; ni++) {
            int c = warp_n * WN + ni * 8 + t * 2;
            if (r0 < M) {
                __half2 hv = __floats2half2_rn(acc[mi][ni][0], acc[mi][ni][1]);
                *(__half2*)&C[(size_t)r0 * N + c] = hv;
            }
            if (r1 < M) {
                __half2 hv = __floats2half2_rn(acc[mi][ni][2], acc[mi][ni][3]);
                *(__half2*)&C[(size_t)r1 * N + c] = hv;
            }
        }
    }
}

// ---------------------------------------------------------------------------
// CSR gather aggregation (no atomics): one warp per node, unroll 4.
// ---------------------------------------------------------------------------
__device__ __forceinline__ void acc_row128(float4& acc, const __half* row,
                                           int lane, float w) {
    uint2 raw = *(const uint2*)&row[lane * 4];
    float2 f0 = __half22float2(*(__half2*)&raw.x);
    float2 f1 = __half22float2(*(__half2*)&raw.y);
    acc.x += f0.x * w; acc.y += f0.y * w; acc.z += f1.x * w; acc.w += f1.y * w;
}

// layer 1: tmp[d,:] = tanh( dinv[d]*sum_s xw[s,:]*dinv[s] + xw[d,:]*dinv[d]^2 + b1 )
__global__ void gather1_kernel(const float* __restrict__ b1) {
    int node = blockIdx.x * (blockDim.x >> 5) + (threadIdx.x >> 5);
    int lane = threadIdx.x & 31;
    if (node >= NN) return;
    int e = g_ptr[node], end = g_ptr[node + 1];
    float dd = g_dinv[node];
    float4 acc = make_float4(0.f, 0.f, 0.f, 0.f);
    for (; e + 4 <= end; e += 4) {
        int s0 = g_esrc[e], s1 = g_esrc[e + 1], s2 = g_esrc[e + 2], s3 = g_esrc[e + 3];
        float w0 = g_dinv[s0], w1 = g_dinv[s1], w2 = g_dinv[s2], w3 = g_dinv[s3];
        acc_row128(acc, &g_xwh[(size_t)s0 * 128], lane, w0);
        acc_row128(acc, &g_xwh[(size_t)s1 * 128], lane, w1);
        acc_row128(acc, &g_xwh[(size_t)s2 * 128], lane, w2);
        acc_row128(acc, &g_xwh[(size_t)s3 * 128], lane, w3);
    }
    for (; e < end; e++) {
        int s = g_esrc[e];
        acc_row128(acc, &g_xwh[(size_t)s * 128], lane, g_dinv[s]);
    }
    float4 self = make_float4(0.f, 0.f, 0.f, 0.f);
    acc_row128(self, &g_xwh[(size_t)node * 128], lane, 1.0f);
    float4 bb = ((const float4*)b1)[lane];
    float dd2 = dd * dd;
    float4 o;
    o.x = tanhf(acc.x * dd + self.x * dd2 + bb.x);
    o.y = tanhf(acc.y * dd + self.y * dd2 + bb.y);
    o.z = tanhf(acc.z * dd + self.z * dd2 + bb.z);
    o.w = tanhf(acc.w * dd + self.w * dd2 + bb.w);
    *(float4*)&g_tmp[(size_t)node * 128 + lane * 4] = o;
}

// layer 2: out[d,:] = dinv[d]*sum_s hw[s,:]*dinv[s] + hw[d,:]*dinv[d]^2 + b2
__global__ void gather2_kernel(const float* __restrict__ b2, float* __restrict__ out) {
    int node = blockIdx.x * (blockDim.x >> 5) + (threadIdx.x >> 5);
    int lane = threadIdx.x & 31;
    if (node >= NN) return;
    int e = g_ptr[node], end = g_ptr[node + 1];
    float dd = g_dinv[node];
    float2 acc = make_float2(0.f, 0.f);
    for (; e + 4 <= end; e += 4) {
        int s0 = g_esrc[e], s1 = g_esrc[e + 1], s2 = g_esrc[e + 2], s3 = g_esrc[e + 3];
        float w0 = g_dinv[s0], w1 = g_dinv[s1], w2 = g_dinv[s2], w3 = g_dinv[s3];
        float2 f0 = __half22float2(*(const __half2*)&g_hwh[(size_t)s0 * 64 + lane * 2]);
        float2 f1 = __half22float2(*(const __half2*)&g_hwh[(size_t)s1 * 64 + lane * 2]);
        float2 f2 = __half22float2(*(const __half2*)&g_hwh[(size_t)s2 * 64 + lane * 2]);
        float2 f3 = __half22float2(*(const __half2*)&g_hwh[(size_t)s3 * 64 + lane * 2]);
        acc.x += f0.x * w0 + f1.x * w1 + f2.x * w2 + f3.x * w3;
        acc.y += f0.y * w0 + f1.y * w1 + f2.y * w2 + f3.y * w3;
    }
    for (; e < end; e++) {
        int s = g_esrc[e];
        float w = g_dinv[s];
        float2 f = __half22float2(*(const __half2*)&g_hwh[(size_t)s * 64 + lane * 2]);
        acc.x += f.x * w; acc.y += f.y * w;
    }
    float2 self = __half22float2(*(const __half2*)&g_hwh[(size_t)node * 64 + lane * 2]);
    float2 bb = ((const float2*)b2)[lane];
    float dd2 = dd * dd;
    float2 o;
    o.x = acc.x * dd + self.x * dd2 + bb.x;
    o.y = acc.y * dd + self.y * dd2 + bb.y;
    *(float2*)&out[(size_t)node * 64 + lane * 2] = o;
}

// ---------------------------------------------------------------------------
extern "C" void kernel_launch(void* const* d_in, const int* in_sizes, int n_in,
                              void* d_out, int out_size) {
    const float* x   = (const float*)d_in[0];
    const int* ei    = (const int*)d_in[1];   // int32 (jax x64 disabled)
    const float* W1  = (const float*)d_in[2];
    const float* b1  = (const float*)d_in[3];
    const float* W2  = (const float*)d_in[4];
    const float* b2  = (const float*)d_in[5];
    float* out       = (float*)d_out;

    const int E = in_sizes[1] / 2;
    const int* src = ei;
    const int* dst = ei + E;

    __half *xwh_p, *hwh_p;
    float *tmp_p;
    cudaGetSymbolAddress((void**)&xwh_p, g_xwh);
    cudaGetSymbolAddress((void**)&tmp_p, g_tmp);
    cudaGetSymbolAddress((void**)&hwh_p, g_hwh);

    // lazily-created side stream + fork/join events (host objects, no device mem)
    static cudaStream_t s2 = nullptr;
    static cudaEvent_t ev_fork = nullptr, ev_join = nullptr;
    if (!s2) {
        cudaStreamCreateWithFlags(&s2, cudaStreamNonBlocking);
        cudaEventCreateWithFlags(&ev_fork, cudaEventDisableTiming);
        cudaEventCreateWithFlags(&ev_join, cudaEventDisableTiming);
    }

    const int T = 256;
    const int E4 = (E + 3) / 4;

    // ---- fork: GEMM1 (independent of CSR build) runs on s2 ----
    cudaEventRecord(ev_fork, 0);
    cudaStreamWaitEvent(s2, ev_fork, 0);
    {
        dim3 grid(1, (NN + 63) / 64);
        mma_gemm_kernel<64, 128, 32, 32, 32><<<grid, 256, 0, s2>>>(
            x, W1, xwh_p, NN, 128, 256);
    }
    cudaEventRecord(ev_join, s2);

    // ---- CSR build chain on default stream (concurrent with GEMM1) ----
    zero_kernel<<<(NN + T - 1) / T, T>>>(NN);
    hist_kernel<<<(E4 + T - 1) / T, T>>>(dst, E);
    scanA_kernel<<<NB, 256>>>();
    scanC_kernel<<<NB, 256>>>();
    fill_kernel<<<(E4 + T - 1) / T, T>>>(src, dst, E);

    // ---- join: gather1 needs both chains ----
    cudaStreamWaitEvent(0, ev_join, 0);
    gather1_kernel<<<(NN + 7) / 8, 256>>>(b1);

    // layer 2: hw = h @ W2 (fp16 store)
    {
        dim3 grid(1, (NN + 63) / 64);
        mma_gemm_kernel<64, 64, 32, 32, 16><<<grid, 256>>>(tmp_p, W2, hwh_p, NN, 64, 128);
    }
    gather2_kernel<<<(NN + 7) / 8, 256>>>(b2, out);
}